// round 17
// baseline (speedup 1.0000x reference)
#include <cuda_runtime.h>
#include <cuda_bf16.h>
#include <cstdint>
#include <math.h>

#define Hh 96
#define Ww 96
#define Bn 4
#define Cc 64
#define HW (Hh*Ww)
#define KK 9
#define CIN2 130
#define NPAIRH 33          // cin-pairs per conv half
#define NST2 17            // conv pipeline stages (2 pairs each)
#define MPIX 128           // pixels per deform block
#define VP 72              // bf16 pitch of V/W tiles (144 B, bank-clean)
#define VMAT (MPIX*VP*2)   // one V matrix: 18432 B
#define WMAT (64*VP*2)     // one W matrix: 9216 B
#define W_OFF (2*VMAT)     // W tiles start after V hi/lo
#define DEF_SMEM (2*VMAT + 2*WMAT)   // 55296 B

// Scratch (device globals)
__device__ float g_fjt[Bn*HW*Cc];                // frame_j as [B,HW,C]
__device__ __nv_bfloat16 g_wpad[KK*2*64*VP];     // W [tap][hi/lo][oc][72]
__device__ float g_wc2[66*28*20];                // conv w reorder
__device__ float g_part[8*28*HW];                // conv partials

// ---------------------------------------------------------------------------
__device__ __forceinline__ unsigned smem_u32(const void* p) {
    return (unsigned)__cvta_generic_to_shared(p);
}
__device__ __forceinline__ void cpa4(unsigned dst, const void* src, bool pred) {
    int sz = pred ? 4 : 0;
    asm volatile("cp.async.ca.shared.global [%0], [%1], 4, %2;\n"
                 :: "r"(dst), "l"(src), "r"(sz));
}
__device__ __forceinline__ void cpa16(unsigned dst, const void* src) {
    asm volatile("cp.async.cg.shared.global [%0], [%1], 16;\n"
                 :: "r"(dst), "l"(src));
}
__device__ __forceinline__ void cpa_commit() {
    asm volatile("cp.async.commit_group;\n");
}
__device__ __forceinline__ unsigned long long ffma2(
    unsigned long long a, unsigned long long b, unsigned long long c) {
    unsigned long long d;
    asm("fma.rn.f32x2 %0, %1, %2, %3;" : "=l"(d) : "l"(a), "l"(b), "l"(c));
    return d;
}
__device__ __forceinline__ float2 unpack2(unsigned long long v) {
    float lo, hi;
    asm("mov.b64 {%0, %1}, %2;" : "=f"(lo), "=f"(hi) : "l"(v));
    return make_float2(lo, hi);
}
__device__ __forceinline__ void ldsm_x4(unsigned* r, unsigned addr) {
    asm volatile("ldmatrix.sync.aligned.m8n8.x4.shared.b16 {%0,%1,%2,%3}, [%4];"
                 : "=r"(r[0]), "=r"(r[1]), "=r"(r[2]), "=r"(r[3]) : "r"(addr));
}
__device__ __forceinline__ void ldsm_x2(unsigned* r, unsigned addr) {
    asm volatile("ldmatrix.sync.aligned.m8n8.x2.shared.b16 {%0,%1}, [%2];"
                 : "=r"(r[0]), "=r"(r[1]) : "r"(addr));
}
__device__ __forceinline__ void hmma(float* d, const unsigned* a, const unsigned* b) {
    asm volatile(
        "mma.sync.aligned.m16n8k16.row.col.f32.bf16.bf16.f32 "
        "{%0,%1,%2,%3}, {%4,%5,%6,%7}, {%8,%9}, {%0,%1,%2,%3};"
        : "+f"(d[0]), "+f"(d[1]), "+f"(d[2]), "+f"(d[3])
        : "r"(a[0]), "r"(a[1]), "r"(a[2]), "r"(a[3]), "r"(b[0]), "r"(b[1]));
}

// ---------------------------------------------------------------------------
// frame_j [B,C,H,W] -> [B,HW,C]
// ---------------------------------------------------------------------------
__global__ void k_transpose(const float* __restrict__ fj) {
    __shared__ float s[64][33];
    int b   = blockIdx.y;
    int hw0 = blockIdx.x * 32;
    int tid = threadIdx.x;
    int tx = tid & 31, ty = tid >> 5;
#pragma unroll
    for (int i = 0; i < 8; i++) {
        int c = ty + i * 8;
        s[c][tx] = fj[(size_t)(b * Cc + c) * HW + hw0 + tx];
    }
    __syncthreads();
    int ci = tid & 63, j4 = tid >> 6;
#pragma unroll
    for (int i = 0; i < 8; i++) {
        int j = j4 + i * 4;
        g_fjt[(size_t)(b * HW + hw0 + j) * Cc + ci] = s[ci][j];
    }
}

// ---------------------------------------------------------------------------
// Weight prep: split w_reg into bf16 hi/lo padded tiles [tap][hi/lo][oc][72],
// plus conv weight reorder (g_wc2).
// ---------------------------------------------------------------------------
__global__ void k_wprep(const float* __restrict__ w_reg,
                        const float* __restrict__ w_off,
                        const float* __restrict__ w_mod) {
    int i = blockIdx.x * 256 + threadIdx.x;
    const int NW = KK * 64 * VP;     // 41472
    if (i < NW) {
        int tap = i / (64 * VP);
        int r   = i % (64 * VP);
        int oc  = r / VP;
        int k   = r % VP;
        float w = (k < 64) ? w_reg[(oc * 64 + k) * KK + tap] : 0.f;
        __nv_bfloat16 hi = __float2bfloat16_rn(w);
        __nv_bfloat16 lo = __float2bfloat16_rn(w - __bfloat162float(hi));
        g_wpad[tap * (2 * 64 * VP) + r] = hi;
        g_wpad[tap * (2 * 64 * VP) + 64 * VP + r] = lo;
    } else if (i < NW + 66 * 560) {
        int j = i - NW;
        int pr = j / 560;
        int r  = j % 560;
        int oc = r / 20;
        int r2 = r % 20;
        int tap = r2 >> 1, c = r2 & 1;
        int cin = 2 * pr + c;
        float v = 0.f;
        if (tap < 9 && oc < 27 && cin < CIN2)
            v = (oc < 18) ? w_off[(oc * CIN2 + cin) * 9 + tap]
                          : w_mod[((oc - 18) * CIN2 + cin) * 9 + tap];
        g_wc2[j] = v;
    }
}

// ---------------------------------------------------------------------------
// Fused 3x3 conv (half the cin reduction per block). Channel-pair FFMA2.
// (Unchanged — best-known configuration.)
// ---------------------------------------------------------------------------
__global__ void __launch_bounds__(256, 2) k_conv(
    const float* __restrict__ fi, const float* __restrict__ fj,
    const float* __restrict__ fl)
{
    __shared__ __align__(16) float s_in[3][2][680];
    __shared__ __align__(16) float s_w[3][2][560];
    int z  = blockIdx.z;
    int b  = z >> 1, half = z & 1;
    int pr_base = half * NPAIRH;
    int x0 = blockIdx.x * 32, y0 = blockIdx.y * 8;
    int tid = threadIdx.x;
    int tx   = tid & 31;
    int warp = tid >> 5;
    int ocg  = warp >> 1;
    int wrow = (warp & 1) * 4;
    int obase = ocg * 7;

    int ily0 = tid / 34,  ilx0 = tid % 34;
    int i1   = tid + 256;
    int ily1 = i1 / 34,   ilx1 = i1 % 34;
    int gy0 = y0 + ily0 - 1, gx0 = x0 + ilx0 - 1;
    int gy1 = y0 + ily1 - 1, gx1 = x0 + ilx1 - 1;
    bool sok0 = (gy0 >= 0 && gy0 < Hh && gx0 >= 0 && gx0 < Ww);
    bool sok1 = (tid < 84) && (gy1 >= 0 && gy1 < Hh && gx1 >= 0 && gx1 < Ww);
    int soff0 = sok0 ? (gy0 * Ww + gx0) : 0;
    int soff1 = sok1 ? (gy1 * Ww + gx1) : 0;

    auto stage = [&](int s, int buf) {
#pragma unroll
        for (int pp = 0; pp < 2; pp++) {
            int lc = 2 * s + pp;
            bool okp = (lc < NPAIRH);
            int pr = pr_base + (okp ? lc : 0);
#pragma unroll
            for (int c = 0; c < 2; c++) {
                int cin = 2 * pr + c;
                bool vc = okp && (cin < CIN2);
                int ci2 = vc ? cin : 128;
                const float* src = (ci2 < 64)  ? fi + (size_t)(b * 64 + ci2) * HW
                                 : (ci2 < 128) ? fj + (size_t)(b * 64 + ci2 - 64) * HW
                                               : fl + (size_t)(b * 2 + ci2 - 128) * HW;
                float* din = s_in[buf][pp];
                cpa4(smem_u32(din + tid * 2 + c), src + soff0, vc && sok0);
                if (tid < 84)
                    cpa4(smem_u32(din + (tid + 256) * 2 + c), src + soff1, vc && sok1);
            }
            const float* wsrc = g_wc2 + (size_t)pr * 560;
            float* dw = s_w[buf][pp];
            cpa4(smem_u32(dw + tid), wsrc + tid, okp);
            cpa4(smem_u32(dw + tid + 256), wsrc + tid + 256, okp);
            if (tid < 48)
                cpa4(smem_u32(dw + tid + 512), wsrc + tid + 512, okp);
        }
    };

    unsigned long long acc2[7][4];
#pragma unroll
    for (int oi = 0; oi < 7; oi++)
#pragma unroll
        for (int px = 0; px < 4; px++) acc2[oi][px] = 0ull;

    stage(0, 0); cpa_commit();
    stage(1, 1); cpa_commit();

    for (int s = 0; s < NST2; s++) {
        if (s < NST2 - 1) asm volatile("cp.async.wait_group 1;\n");
        else              asm volatile("cp.async.wait_group 0;\n");
        __syncthreads();
        int buf = s % 3;
#pragma unroll
        for (int pp = 0; pp < 2; pp++) {
            const float* sb = s_in[buf][pp] + (wrow * 34 + tx) * 2;
            unsigned long long t2[6][3];
#pragma unroll
            for (int jr = 0; jr < 6; jr++)
#pragma unroll
                for (int jc = 0; jc < 3; jc++)
                    t2[jr][jc] = *(const unsigned long long*)(sb + (jr * 34 + jc) * 2);

            const float* swb = s_w[buf][pp];
#pragma unroll
            for (int oi = 0; oi < 7; oi++) {
                const float* wr = swb + (obase + oi) * 20;
                ulonglong2 wA = *(const ulonglong2*)wr;
                ulonglong2 wB = *(const ulonglong2*)(wr + 4);
                ulonglong2 wC = *(const ulonglong2*)(wr + 8);
                ulonglong2 wD = *(const ulonglong2*)(wr + 12);
                unsigned long long w8 = *(const unsigned long long*)(wr + 16);
#pragma unroll
                for (int px = 0; px < 4; px++) {
                    unsigned long long a = acc2[oi][px];
                    a = ffma2(t2[px + 0][0], wA.x, a);
                    a = ffma2(t2[px + 0][1], wA.y, a);
                    a = ffma2(t2[px + 0][2], wB.x, a);
                    a = ffma2(t2[px + 1][0], wB.y, a);
                    a = ffma2(t2[px + 1][1], wC.x, a);
                    a = ffma2(t2[px + 1][2], wC.y, a);
                    a = ffma2(t2[px + 2][0], wD.x, a);
                    a = ffma2(t2[px + 2][1], wD.y, a);
                    a = ffma2(t2[px + 2][2], w8, a);
                    acc2[oi][px] = a;
                }
            }
        }
        if (s + 2 < NST2) { stage(s + 2, (s + 2) % 3); cpa_commit(); }
    }

#pragma unroll
    for (int oi = 0; oi < 7; oi++) {
        float* dst = g_part + ((size_t)z * 28 + obase + oi) * HW;
#pragma unroll
        for (int px = 0; px < 4; px++) {
            float2 u = unpack2(acc2[oi][px]);
            dst[(y0 + wrow + px) * Ww + x0 + tx] = u.x + u.y;
        }
    }
}

// ---------------------------------------------------------------------------
// Deformable conv via mma.sync (HMMA) bf16 split-precision.
// Block = 128 pixels x 64 ocs, 256 threads (8 warps).
// A = weights [64 oc][k] (4 m-tiles), B = gathered values [pix][k] (warp: 2
// n-tiles of its 16 pixels). K=576 over 9 taps x 4 k-chunks, 3 hi/lo passes.
// ---------------------------------------------------------------------------
__global__ void __launch_bounds__(256, 2) k_deform(
    float* __restrict__ out,
    const float* __restrict__ b_off, const float* __restrict__ b_mod)
{
    extern __shared__ __align__(1024) char dsm[];
    unsigned dbase = smem_u32(dsm);

    int tid  = threadIdx.x;
    int b    = blockIdx.y;
    int p0   = blockIdx.x * MPIX;
    int warp = tid >> 5;
    int lane = tid & 31;

    const float* P0 = g_part + (size_t)(b * 2)     * 28 * HW;
    const float* P1 = g_part + (size_t)(b * 2 + 1) * 28 * HW;
    const float* fb = g_fjt + (size_t)b * HW * Cc;

    // gather mapping: 2 threads per pixel, 8 channel-quads each
    int gp  = tid >> 1;
    int hq  = (tid & 1) * 8;
    int gpp = p0 + gp;
    int gy  = gpp / Ww, gx = gpp % Ww;

    // ldmatrix per-lane address components
    int rowA = lane & 15;              // W rows (x4)
    int colA = (lane >> 4) * 8;
    int rowB = lane & 7;               // V rows (x2)
    int colB = ((lane >> 3) & 1) * 8;

    float acc[4][2][4];
#pragma unroll
    for (int mt = 0; mt < 4; mt++)
#pragma unroll
        for (int nt = 0; nt < 2; nt++)
#pragma unroll
            for (int e = 0; e < 4; e++) acc[mt][nt][e] = 0.f;

    for (int tap = 0; tap < 9; tap++) {
        if (tap > 0) __syncthreads();   // previous MMA reads done

        // stage W hi/lo (18432 B) via cp.async
        {
            const char* src = (const char*)(g_wpad + (size_t)tap * 2 * 64 * VP);
#pragma unroll
            for (int i = 0; i < 5; i++) {
                int idx = tid + i * 256;
                if (idx < 1152)
                    cpa16(dbase + W_OFF + idx * 16, src + idx * 16);
            }
            cpa_commit();
        }
        // gather -> V hi/lo bf16 tiles
        {
            float offy = P0[(2 * tap)     * HW + gpp] + P1[(2 * tap)     * HW + gpp]
                       + b_off[2 * tap];
            float offx = P0[(2 * tap + 1) * HW + gpp] + P1[(2 * tap + 1) * HW + gpp]
                       + b_off[2 * tap + 1];
            float zz   = P0[(18 + tap)    * HW + gpp] + P1[(18 + tap)    * HW + gpp]
                       + b_mod[tap];
            float m = 2.f / (1.f + expf(-zz));
            int ky = tap / 3, kx = tap % 3;
            float py = (float)(gy - 1 + ky) + offy;
            float px = (float)(gx - 1 + kx) + offx;
            float fy = floorf(py), fx = floorf(px);
            int y0i = (int)fy, x0i = (int)fx;
            float wy = py - fy, wx = px - fx;
            float cw[4];
            int   ci[4];
#pragma unroll
            for (int d = 0; d < 4; d++) {
                int dy = d >> 1, dx = d & 1;
                int yc = y0i + dy, xc = x0i + dx;
                bool ok = (yc >= 0) && (yc < Hh) && (xc >= 0) && (xc < Ww);
                float w = (dy ? wy : 1.f - wy) * (dx ? wx : 1.f - wx) * m;
                cw[d] = ok ? w : 0.f;
                int ycc = min(max(yc, 0), Hh - 1);
                int xcc = min(max(xc, 0), Ww - 1);
                ci[d] = ycc * Ww + xcc;
            }
            const float* pp0 = fb + (size_t)ci[0] * Cc;
            const float* pp1 = fb + (size_t)ci[1] * Cc;
            const float* pp2 = fb + (size_t)ci[2] * Cc;
            const float* pp3 = fb + (size_t)ci[3] * Cc;
            float w0 = cw[0], w1 = cw[1], w2 = cw[2], w3 = cw[3];
            char* vh = dsm + gp * (VP * 2);
            char* vl = vh + VMAT;
#pragma unroll
            for (int k = 0; k < 8; k++) {
                int q = hq + k;
                float4 f0 = *(const float4*)(pp0 + q * 4);
                float4 f1 = *(const float4*)(pp1 + q * 4);
                float4 f2 = *(const float4*)(pp2 + q * 4);
                float4 f3 = *(const float4*)(pp3 + q * 4);
                float4 v;
                v.x = w0 * f0.x + w1 * f1.x + w2 * f2.x + w3 * f3.x;
                v.y = w0 * f0.y + w1 * f1.y + w2 * f2.y + w3 * f3.y;
                v.z = w0 * f0.z + w1 * f1.z + w2 * f2.z + w3 * f3.z;
                v.w = w0 * f0.w + w1 * f1.w + w2 * f2.w + w3 * f3.w;
                __nv_bfloat162 h01 = __float22bfloat162_rn(make_float2(v.x, v.y));
                __nv_bfloat162 h23 = __float22bfloat162_rn(make_float2(v.z, v.w));
                float2 hf01 = __bfloat1622float2(h01);
                float2 hf23 = __bfloat1622float2(h23);
                __nv_bfloat162 l01 = __float22bfloat162_rn(
                    make_float2(v.x - hf01.x, v.y - hf01.y));
                __nv_bfloat162 l23 = __float22bfloat162_rn(
                    make_float2(v.z - hf23.x, v.w - hf23.y));
                uint2 uh, ul;
                uh.x = *(const unsigned*)&h01;  uh.y = *(const unsigned*)&h23;
                ul.x = *(const unsigned*)&l01;  ul.y = *(const unsigned*)&l23;
                *(uint2*)(vh + q * 8) = uh;
                *(uint2*)(vl + q * 8) = ul;
            }
        }
        asm volatile("cp.async.wait_group 0;\n" ::: "memory");
        __syncthreads();

        // MMA: 4 kchunks x (4 mtiles x 2 ntiles) x {hh, hl, lh}
        unsigned vb = dbase;
        unsigned wb = dbase + W_OFF;
#pragma unroll
        for (int kc = 0; kc < 4; kc++) {
            unsigned bh[2][2], bl[2][2];
#pragma unroll
            for (int nt = 0; nt < 2; nt++) {
                unsigned baddr = vb + (warp * 16 + nt * 8 + rowB) * (VP * 2)
                               + (kc * 16 + colB) * 2;
                ldsm_x2(bh[nt], baddr);
                ldsm_x2(bl[nt], baddr + VMAT);
            }
#pragma unroll
            for (int mt = 0; mt < 4; mt++) {
                unsigned ah[4], al[4];
                unsigned aaddr = wb + (mt * 16 + rowA) * (VP * 2)
                               + (kc * 16 + colA) * 2;
                ldsm_x4(ah, aaddr);
                ldsm_x4(al, aaddr + WMAT);
#pragma unroll
                for (int nt = 0; nt < 2; nt++) {
                    hmma(acc[mt][nt], ah, bh[nt]);
                    hmma(acc[mt][nt], ah, bl[nt]);
                    hmma(acc[mt][nt], al, bh[nt]);
                }
            }
        }
    }

    // epilogue: D[oc][pix] direct stores (float2 per fragment row)
#pragma unroll
    for (int mt = 0; mt < 4; mt++) {
#pragma unroll
        for (int nt = 0; nt < 2; nt++) {
            int oc0  = mt * 16 + (lane >> 2);
            int pixb = p0 + warp * 16 + nt * 8 + 2 * (lane & 3);
            float2 v0 = make_float2(acc[mt][nt][0], acc[mt][nt][1]);
            float2 v1 = make_float2(acc[mt][nt][2], acc[mt][nt][3]);
            *(float2*)(out + (size_t)(b * 64 + oc0)     * HW + pixb) = v0;
            *(float2*)(out + (size_t)(b * 64 + oc0 + 8) * HW + pixb) = v1;
        }
    }
}

// ---------------------------------------------------------------------------
extern "C" void kernel_launch(void* const* d_in, const int* in_sizes, int n_in,
                              void* d_out, int out_size) {
    const float* frame_i = (const float*)d_in[0];
    const float* frame_j = (const float*)d_in[1];
    const float* flow_ij = (const float*)d_in[2];
    const float* w_off   = (const float*)d_in[3];
    const float* b_off   = (const float*)d_in[4];
    const float* w_mod   = (const float*)d_in[5];
    const float* b_mod   = (const float*)d_in[6];
    const float* w_reg   = (const float*)d_in[7];
    float* out = (float*)d_out;

    cudaFuncSetAttribute(k_deform, cudaFuncAttributeMaxDynamicSharedMemorySize,
                         DEF_SMEM);

    k_transpose<<<dim3(HW / 32, Bn), 256>>>(frame_j);
    k_wprep<<<(KK * 64 * VP + 66 * 560 + 255) / 256, 256>>>(w_reg, w_off, w_mod);
    k_conv<<<dim3(Ww / 32, Hh / 8, Bn * 2), 256>>>(frame_i, frame_j, flow_ij);
    k_deform<<<dim3(HW / MPIX, Bn), 256, DEF_SMEM>>>(out, b_off, b_mod);
}